// round 1
// baseline (speedup 1.0000x reference)
#include <cuda_runtime.h>
#include <math.h>
#include <float.h>

#define D 256
#define C 128
#define B_MAX 131072
#define SORT_BLK 512
#define NB_MAX (B_MAX / SORT_BLK)

#define TILE_R 64
#define WT_STRIDE 132   // 128 + 4 pad: conflict-mitigated transposed store, 16B-aligned rows
#define ET_STRIDE 68    // 64 + 4 pad
#define SMEM_BYTES ((D * WT_STRIDE + D * ET_STRIDE) * 4)

// ---------------- scratch (static device globals; no allocation) ----------------
__device__ int    g_tneg[B_MAX];
__device__ int    g_rank[B_MAX];
__device__ int    g_order[B_MAX];
__device__ int    g_counts[C];
__device__ int    g_starts[C];
__device__ int    g_blockhist[NB_MAX][C];
__device__ double g_loss_sum;
__device__ int    g_valid_cnt;

// ---------------- init: zero per-launch accumulators (graph replays!) -----------
__global__ void init_kernel() {
    int t = threadIdx.x;
    if (t < C) g_counts[t] = 0;
    if (t == 0) { g_loss_sum = 0.0; g_valid_cnt = 0; }
}

// ---------------- top-2 insert (matches jax top_k tie order: lower idx wins) ----
__device__ __forceinline__ void top2_insert(float v, int idx,
                                            float& v1, int& i1, float& v2, int& i2) {
    if (v > v1 || (v == v1 && idx < i1)) {
        v2 = v1; i2 = i1; v1 = v; i1 = idx;
    } else if (v > v2 || (v == v2 && idx < i2)) {
        v2 = v; i2 = idx;
    }
}

// ---------------- K1: fp32 logits GEMM + top2 + target_neg ----------------------
// Block: 256 threads. smem: W^T [256][132], e^T tile [256][68].
// Thread (tx=tid&31, ty=tid>>5): 8 rows (8*ty..) x 4 classes (4*tx..) register tile.
__global__ void logits_top2_kernel(const float* __restrict__ emb,
                                   const int*   __restrict__ labels,
                                   const float* __restrict__ W,
                                   const float* __restrict__ b,
                                   int B, int rowsPerBlock) {
    extern __shared__ float smem[];
    float* WT = smem;                    // [k][c] stride WT_STRIDE
    float* eT = smem + D * WT_STRIDE;    // [k][r] stride ET_STRIDE

    const int tid = threadIdx.x;
    const int tx = tid & 31;
    const int ty = tid >> 5;

    // Load W transposed (one-time per block). Global read coalesced.
    for (int idx = tid; idx < C * D; idx += 256) {
        int c = idx >> 8;        // row of W
        int k = idx & 255;       // column
        WT[k * WT_STRIDE + c] = W[idx];
    }

    const int rowBase0 = blockIdx.x * rowsPerBlock;

    for (int t0 = 0; t0 < rowsPerBlock; t0 += TILE_R) {
        const int rowBase = rowBase0 + t0;
        if (rowBase >= B) break;

        __syncthreads();  // WT ready (first iter) / previous tile consumed
        for (int idx = tid; idx < TILE_R * D; idx += 256) {
            int r = idx >> 8;
            int k = idx & 255;
            int gr = rowBase + r;
            eT[k * ET_STRIDE + r] = (gr < B) ? emb[(size_t)gr * D + k] : 0.0f;
        }
        __syncthreads();

        float acc[8][4];
#pragma unroll
        for (int r = 0; r < 8; r++)
#pragma unroll
            for (int j = 0; j < 4; j++) acc[r][j] = 0.0f;

#pragma unroll 2
        for (int k0 = 0; k0 < D; k0 += 4) {
#pragma unroll
            for (int kk = 0; kk < 4; kk++) {
                const int k = k0 + kk;
                const float4 w  = *(const float4*)&WT[k * WT_STRIDE + 4 * tx];
                const float4 ea = *(const float4*)&eT[k * ET_STRIDE + 8 * ty];
                const float4 eb = *(const float4*)&eT[k * ET_STRIDE + 8 * ty + 4];
                acc[0][0] += ea.x * w.x; acc[0][1] += ea.x * w.y; acc[0][2] += ea.x * w.z; acc[0][3] += ea.x * w.w;
                acc[1][0] += ea.y * w.x; acc[1][1] += ea.y * w.y; acc[1][2] += ea.y * w.z; acc[1][3] += ea.y * w.w;
                acc[2][0] += ea.z * w.x; acc[2][1] += ea.z * w.y; acc[2][2] += ea.z * w.z; acc[2][3] += ea.z * w.w;
                acc[3][0] += ea.w * w.x; acc[3][1] += ea.w * w.y; acc[3][2] += ea.w * w.z; acc[3][3] += ea.w * w.w;
                acc[4][0] += eb.x * w.x; acc[4][1] += eb.x * w.y; acc[4][2] += eb.x * w.z; acc[4][3] += eb.x * w.w;
                acc[5][0] += eb.y * w.x; acc[5][1] += eb.y * w.y; acc[5][2] += eb.y * w.z; acc[5][3] += eb.y * w.w;
                acc[6][0] += eb.z * w.x; acc[6][1] += eb.z * w.y; acc[6][2] += eb.z * w.z; acc[6][3] += eb.z * w.w;
                acc[7][0] += eb.w * w.x; acc[7][1] += eb.w * w.y; acc[7][2] += eb.w * w.z; acc[7][3] += eb.w * w.w;
            }
        }

        const float4 bb = *(const float4*)&b[4 * tx];

#pragma unroll
        for (int r = 0; r < 8; r++) {
            acc[r][0] += bb.x; acc[r][1] += bb.y; acc[r][2] += bb.z; acc[r][3] += bb.w;

            float v1 = -FLT_MAX, v2 = -FLT_MAX;
            int   i1 = 0x7fffffff, i2 = 0x7fffffff;
            top2_insert(acc[r][0], 4 * tx + 0, v1, i1, v2, i2);
            top2_insert(acc[r][1], 4 * tx + 1, v1, i1, v2, i2);
            top2_insert(acc[r][2], 4 * tx + 2, v1, i1, v2, i2);
            top2_insert(acc[r][3], 4 * tx + 3, v1, i1, v2, i2);

#pragma unroll
            for (int off = 16; off > 0; off >>= 1) {
                float ov1 = __shfl_xor_sync(0xffffffffu, v1, off);
                int   oi1 = __shfl_xor_sync(0xffffffffu, i1, off);
                float ov2 = __shfl_xor_sync(0xffffffffu, v2, off);
                int   oi2 = __shfl_xor_sync(0xffffffffu, i2, off);
                top2_insert(ov1, oi1, v1, i1, v2, i2);
                top2_insert(ov2, oi2, v1, i1, v2, i2);
            }

            const int gr = rowBase + 8 * ty + r;
            if (tx == 0 && gr < B) {
                int lab = labels[gr];
                g_tneg[gr] = (i1 == lab) ? i2 : i1;
            }
        }
    }
}

// ---------------- K2: per-block label histogram + global counts -----------------
__global__ void hist_kernel(const int* __restrict__ labels, int B) {
    __shared__ int h[C];
    const int tid = threadIdx.x;
    if (tid < C) h[tid] = 0;
    __syncthreads();
    const int i = blockIdx.x * SORT_BLK + tid;
    if (i < B) atomicAdd(&h[labels[i]], 1);
    __syncthreads();
    if (tid < C) {
        g_blockhist[blockIdx.x][tid] = h[tid];
        atomicAdd(&g_counts[tid], h[tid]);
    }
}

// ---------------- K3: per-bin exclusive scan over blocks + starts ---------------
__global__ void scan_kernel(int NB) {
    const int c = threadIdx.x;  // 128 threads
    int run = 0;
    for (int bb = 0; bb < NB; bb++) {
        int v = g_blockhist[bb][c];
        g_blockhist[bb][c] = run;
        run += v;
    }
    __shared__ int cnt[C];
    cnt[c] = run;
    __syncthreads();
    if (c == 0) {
        int s = 0;
        for (int j = 0; j < C; j++) { g_starts[j] = s; s += cnt[j]; }
    }
}

// ---------------- K4: stable rank within label + scatter order ------------------
__global__ void rank_order_kernel(const int* __restrict__ labels, int B) {
    __shared__ int ls[SORT_BLK];
    const int tid = threadIdx.x;
    const int i = blockIdx.x * SORT_BLK + tid;
    const int lab = (i < B) ? labels[i] : -1;
    ls[tid] = lab;
    __syncthreads();
    if (i < B) {
        int local = 0;
        for (int j = 0; j < SORT_BLK; j++)          // uniform bound -> smem broadcast
            local += (j < tid && ls[j] == lab);
        const int rank = g_blockhist[blockIdx.x][lab] + local;
        g_rank[i] = rank;
        g_order[g_starts[lab] + rank] = i;
    }
}

// ---------------- K5: sample pos/neg, distances, hinge loss, reduce -------------
__global__ void dist_kernel(const float* __restrict__ emb,
                            const int*   __restrict__ labels,
                            const int*   __restrict__ r_pos,
                            const int*   __restrict__ r_neg,
                            int B) {
    __shared__ double s_loss;
    __shared__ int s_valid;
    if (threadIdx.x == 0) { s_loss = 0.0; s_valid = 0; }
    __syncthreads();

    const int lane = threadIdx.x & 31;
    const int i = (blockIdx.x * blockDim.x + threadIdx.x) >> 5;   // one row per warp

    float loss = 0.0f;
    int valid = 0;

    if (i < B) {
        const int lab = labels[i];
        const int tn  = g_tneg[i];
        const int n_pos = g_counts[lab] - 1;
        const int n_neg = g_counts[tn];

        int pr = r_pos[i] % max(n_pos, 1);
        pr += (pr >= g_rank[i]) ? 1 : 0;
        const int pidx = g_order[min(g_starts[lab] + pr, B - 1)];

        const int nr = r_neg[i] % max(n_neg, 1);
        const int nidx = g_order[min(g_starts[tn] + nr, B - 1)];

        const float4* ei = (const float4*)(emb + (size_t)i    * D);
        const float4* ep = (const float4*)(emb + (size_t)pidx * D);
        const float4* en = (const float4*)(emb + (size_t)nidx * D);

        float dp = 0.0f, dn = 0.0f;
#pragma unroll
        for (int k = lane; k < D / 4; k += 32) {   // 64 float4 per row, 2 per lane
            const float4 a = ei[k];
            const float4 p = ep[k];
            const float4 n4 = en[k];
            float dx;
            dx = a.x - p.x;  dp += dx * dx;
            dx = a.y - p.y;  dp += dx * dx;
            dx = a.z - p.z;  dp += dx * dx;
            dx = a.w - p.w;  dp += dx * dx;
            dx = a.x - n4.x; dn += dx * dx;
            dx = a.y - n4.y; dn += dx * dx;
            dx = a.z - n4.z; dn += dx * dx;
            dx = a.w - n4.w; dn += dx * dx;
        }
#pragma unroll
        for (int off = 16; off > 0; off >>= 1) {
            dp += __shfl_xor_sync(0xffffffffu, dp, off);
            dn += __shfl_xor_sync(0xffffffffu, dn, off);
        }
        if (lane == 0) {
            valid = (n_pos > 0 && n_neg > 0) ? 1 : 0;
            float l = sqrtf(dp) - sqrtf(dn) + 1.0f;   // MARGIN = 1.0
            loss = (l > 0.0f ? l : 0.0f) * (float)valid;
        }
    }

    if (lane == 0 && i < B) {
        atomicAdd(&s_loss, (double)loss);
        atomicAdd(&s_valid, valid);
    }
    __syncthreads();
    if (threadIdx.x == 0) {
        atomicAdd(&g_loss_sum, s_loss);
        atomicAdd(&g_valid_cnt, s_valid);
    }
}

// ---------------- K6: finalize scalar -------------------------------------------
__global__ void finalize_kernel(float* __restrict__ out) {
    out[0] = (float)(g_loss_sum / (double)max(g_valid_cnt, 1));
}

// ---------------- launch ---------------------------------------------------------
extern "C" void kernel_launch(void* const* d_in, const int* in_sizes, int n_in,
                              void* d_out, int out_size) {
    const float* emb    = (const float*)d_in[0];
    const int*   labels = (const int*)  d_in[1];
    const float* W      = (const float*)d_in[2];
    const float* b      = (const float*)d_in[3];
    const int*   r_pos  = (const int*)  d_in[4];
    const int*   r_neg  = (const int*)  d_in[5];
    float*       out    = (float*)d_out;

    const int B = in_sizes[1];

    cudaFuncSetAttribute(logits_top2_kernel,
                         cudaFuncAttributeMaxDynamicSharedMemorySize, SMEM_BYTES);

    init_kernel<<<1, 128>>>();

    const int nblk = 512;
    int rowsPerBlock = (B + nblk - 1) / nblk;
    rowsPerBlock = ((rowsPerBlock + TILE_R - 1) / TILE_R) * TILE_R;
    logits_top2_kernel<<<nblk, 256, SMEM_BYTES>>>(emb, labels, W, b, B, rowsPerBlock);

    const int NB = (B + SORT_BLK - 1) / SORT_BLK;
    hist_kernel<<<NB, SORT_BLK>>>(labels, B);
    scan_kernel<<<1, C>>>(NB);
    rank_order_kernel<<<NB, SORT_BLK>>>(labels, B);

    dist_kernel<<<(B + 7) / 8, 256>>>(emb, labels, r_pos, r_neg, B);
    finalize_kernel<<<1, 1>>>(out);
}

// round 3
// speedup vs baseline: 2.4855x; 2.4855x over previous
#include <cuda_runtime.h>
#include <cuda_bf16.h>
#include <math.h>
#include <float.h>
#include <stdint.h>

#define D 256
#define C 128
#define B_MAX 131072
#define SORT_BLK 512
#define NB_MAX (B_MAX / SORT_BLK)

// ---------------- scratch (static device globals; no allocation) ----------------
__device__ int    g_tneg[B_MAX];
__device__ int    g_rank[B_MAX];
__device__ int    g_order[B_MAX];
__device__ int    g_counts[C];
__device__ int    g_starts[C];
__device__ int    g_bh[C][NB_MAX];        // transposed block hist -> exclusive offsets
__device__ double g_loss_sum;
__device__ int    g_valid_cnt;
__device__ __align__(16) __nv_bfloat16 g_Whi[C * D];
__device__ __align__(16) __nv_bfloat16 g_Wlo[C * D];

// ---------------- init: zero per-launch accumulators (graph replays!) -----------
__global__ void init_kernel() {
    int t = threadIdx.x;
    if (t < C) g_counts[t] = 0;
    if (t == 0) { g_loss_sum = 0.0; g_valid_cnt = 0; }
}

// ---------------- W split: fp32 -> bf16 hi/lo ------------------------------------
__global__ void prep_w_kernel(const float* __restrict__ W) {
    int i = blockIdx.x * 256 + threadIdx.x;   // grid covers C*D = 32768
    float f = W[i];
    __nv_bfloat16 h = __float2bfloat16(f);
    g_Whi[i] = h;
    g_Wlo[i] = __float2bfloat16(f - __bfloat162float(h));
}

// ---------------- helpers ---------------------------------------------------------
__device__ __forceinline__ void top2_insert(float v, int idx,
                                            float& v1, int& i1, float& v2, int& i2) {
    if (v > v1 || (v == v1 && idx < i1)) {
        v2 = v1; i2 = i1; v1 = v; i1 = idx;
    } else if (v > v2 || (v == v2 && idx < i2)) {
        v2 = v; i2 = idx;
    }
}

__device__ __forceinline__ void mma16816(float* c, const uint32_t* a, const uint32_t* b) {
    asm volatile(
        "mma.sync.aligned.m16n8k16.row.col.f32.bf16.bf16.f32 "
        "{%0,%1,%2,%3}, {%4,%5,%6,%7}, {%8,%9}, {%0,%1,%2,%3};"
        : "+f"(c[0]), "+f"(c[1]), "+f"(c[2]), "+f"(c[3])
        : "r"(a[0]), "r"(a[1]), "r"(a[2]), "r"(a[3]), "r"(b[0]), "r"(b[1]));
}

__device__ __forceinline__ void split8(const float* f, uint4& hi, uint4& lo) {
    uint32_t hw[4], lw[4];
#pragma unroll
    for (int j = 0; j < 4; j++) {
        float a = f[2 * j], b2 = f[2 * j + 1];
        __nv_bfloat16 ha = __float2bfloat16(a), hb = __float2bfloat16(b2);
        __nv_bfloat16 la = __float2bfloat16(a - __bfloat162float(ha));
        __nv_bfloat16 lb = __float2bfloat16(b2 - __bfloat162float(hb));
        hw[j] = (uint32_t)__bfloat16_as_ushort(ha) | ((uint32_t)__bfloat16_as_ushort(hb) << 16);
        lw[j] = (uint32_t)__bfloat16_as_ushort(la) | ((uint32_t)__bfloat16_as_ushort(lb) << 16);
    }
    hi = make_uint4(hw[0], hw[1], hw[2], hw[3]);
    lo = make_uint4(lw[0], lw[1], lw[2], lw[3]);
}

// =================== K1: HMMA bf16-split logits GEMM + top2 =====================
// CTA = 256 threads (8 warps), tile M=128 x N=128, K=256 in 2 chunks of 128.
// smem (bytes): bias 512 | red 4096 | Ahi/Alo/Whi/Wlo 4 x 34816 (stride 136 bf16)
#define TILE_BYTES 34816           // 128 rows * 136 elems * 2B
#define ROW_BYTES  272             // 136 * 2
#define OFF_A      4608
#define GEMM_SMEM  (OFF_A + 4 * TILE_BYTES)   // 143,872 B

__global__ void __launch_bounds__(256, 1)
logits_top2_kernel(const float* __restrict__ emb,
                   const int*   __restrict__ labels,
                   const float* __restrict__ b,
                   int B) {
    extern __shared__ char smem[];
    float* sm_bias = (float*)smem;                   // 128 floats
    float* red_v1  = (float*)(smem + 512);           // [2][128]
    int*   red_i1  = (int*)  (smem + 512 + 1024);
    float* red_v2  = (float*)(smem + 512 + 2048);
    int*   red_i2  = (int*)  (smem + 512 + 3072);
    char* Ahi = smem + OFF_A;
    char* Alo = Ahi + TILE_BYTES;
    char* Whi = Alo + TILE_BYTES;
    char* Wlo = Whi + TILE_BYTES;

    const int tid = threadIdx.x;
    const int wid = tid >> 5, lane = tid & 31;
    const int warp_m = wid & 3, warp_n = wid >> 2;
    const int g = lane >> 2, t = lane & 3;
    const int m0 = warp_m * 32, n0 = warp_n * 64;
    const int mBase = blockIdx.x * 128;

    if (tid < C) sm_bias[tid] = b[tid];

    float acc[2][8][4];
#pragma unroll
    for (int mi = 0; mi < 2; mi++)
#pragma unroll
        for (int ni = 0; ni < 8; ni++)
#pragma unroll
            for (int cc = 0; cc < 4; cc++) acc[mi][ni][cc] = 0.0f;

    for (int h = 0; h < 2; h++) {
        __syncthreads();   // previous chunk fully consumed before overwrite

        // A chunk: load fp32, split, store bf16 hi/lo (padded stride)
#pragma unroll
        for (int it = 0; it < 8; it++) {
            int gi = it * 256 + tid;          // 2048 groups of 8 floats
            int row = gi >> 4;
            int k8 = (gi & 15) * 8;
            int gr = mBase + row;
            float f8[8];
            if (gr < B) {
                const float* p = emb + (size_t)gr * D + h * 128 + k8;
                *(float4*)f8       = *(const float4*)p;
                *(float4*)(f8 + 4) = *(const float4*)(p + 4);
            } else {
#pragma unroll
                for (int j = 0; j < 8; j++) f8[j] = 0.0f;
            }
            uint4 hi, lo; split8(f8, hi, lo);
            *(uint4*)(Ahi + row * ROW_BYTES + k8 * 2) = hi;
            *(uint4*)(Alo + row * ROW_BYTES + k8 * 2) = lo;
        }
        // W chunk: copy prepped bf16
#pragma unroll
        for (int it = 0; it < 8; it++) {
            int gi = it * 256 + tid;
            int row = gi >> 4;
            int k8 = (gi & 15) * 8;
            *(uint4*)(Whi + row * ROW_BYTES + k8 * 2) =
                *(const uint4*)(g_Whi + row * D + h * 128 + k8);
            *(uint4*)(Wlo + row * ROW_BYTES + k8 * 2) =
                *(const uint4*)(g_Wlo + row * D + h * 128 + k8);
        }
        __syncthreads();

#pragma unroll
        for (int pass = 0; pass < 3; pass++) {
            const char* Ab = (pass == 2) ? Alo : Ahi;
            const char* Wb = (pass == 1) ? Wlo : Whi;
#pragma unroll
            for (int ks = 0; ks < 8; ks++) {
                const int k0 = ks * 16;
                uint32_t a[2][4], bb[8][2];
#pragma unroll
                for (int mi = 0; mi < 2; mi++) {
                    const char* base = Ab + (m0 + mi * 16 + g) * ROW_BYTES + (k0 + 2 * t) * 2;
                    a[mi][0] = *(const uint32_t*)base;
                    a[mi][1] = *(const uint32_t*)(base + 8 * ROW_BYTES);
                    a[mi][2] = *(const uint32_t*)(base + 16);
                    a[mi][3] = *(const uint32_t*)(base + 8 * ROW_BYTES + 16);
                }
#pragma unroll
                for (int ni = 0; ni < 8; ni++) {
                    const char* base = Wb + (n0 + ni * 8 + g) * ROW_BYTES + (k0 + 2 * t) * 2;
                    bb[ni][0] = *(const uint32_t*)base;
                    bb[ni][1] = *(const uint32_t*)(base + 16);
                }
#pragma unroll
                for (int mi = 0; mi < 2; mi++)
#pragma unroll
                    for (int ni = 0; ni < 8; ni++)
                        mma16816(acc[mi][ni], a[mi], bb[ni]);
            }
        }
    }

    // Epilogue: per-thread top2 over its 16 cols per row, quad-reduce, half-merge.
#pragma unroll
    for (int mi = 0; mi < 2; mi++) {
#pragma unroll
        for (int rh = 0; rh < 2; rh++) {
            float v1 = -FLT_MAX, v2 = -FLT_MAX;
            int i1 = 0x7fffffff, i2 = 0x7fffffff;
#pragma unroll
            for (int ni = 0; ni < 8; ni++) {
#pragma unroll
                for (int cc = 0; cc < 2; cc++) {
                    int col = n0 + ni * 8 + 2 * t + cc;
                    float v = acc[mi][ni][rh * 2 + cc] + sm_bias[col];
                    top2_insert(v, col, v1, i1, v2, i2);
                }
            }
#pragma unroll
            for (int off = 1; off < 4; off <<= 1) {
                float ov1 = __shfl_xor_sync(0xffffffffu, v1, off);
                int   oi1 = __shfl_xor_sync(0xffffffffu, i1, off);
                float ov2 = __shfl_xor_sync(0xffffffffu, v2, off);
                int   oi2 = __shfl_xor_sync(0xffffffffu, i2, off);
                top2_insert(ov1, oi1, v1, i1, v2, i2);
                top2_insert(ov2, oi2, v1, i1, v2, i2);
            }
            if (t == 0) {
                int row = m0 + mi * 16 + rh * 8 + g;
                red_v1[warp_n * 128 + row] = v1;
                red_i1[warp_n * 128 + row] = i1;
                red_v2[warp_n * 128 + row] = v2;
                red_i2[warp_n * 128 + row] = i2;
            }
        }
    }
    __syncthreads();

    if (tid < 128) {
        const int row = tid;
        float v1 = red_v1[row];
        int   i1 = red_i1[row];
        float v2 = red_v2[row];
        int   i2 = red_i2[row];
        top2_insert(red_v1[128 + row], red_i1[128 + row], v1, i1, v2, i2);
        top2_insert(red_v2[128 + row], red_i2[128 + row], v1, i1, v2, i2);
        const int gr = mBase + row;
        if (gr < B) {
            int lab = labels[gr];
            g_tneg[gr] = (i1 == lab) ? i2 : i1;
        }
    }
}

// ---------------- K2: per-block label histogram (transposed) --------------------
__global__ void hist_kernel(const int* __restrict__ labels, int B) {
    __shared__ int h[C];
    const int tid = threadIdx.x;
    if (tid < C) h[tid] = 0;
    __syncthreads();
    const int i = blockIdx.x * SORT_BLK + tid;
    if (i < B) atomicAdd(&h[labels[i]], 1);
    __syncthreads();
    if (tid < C) {
        g_bh[tid][blockIdx.x] = h[tid];
        atomicAdd(&g_counts[tid], h[tid]);
    }
}

// ---------------- K3: per-class exclusive scan over blocks + starts -------------
__global__ void scan_kernel(int NB) {
    const int c = threadIdx.x;          // 128 threads
    const int lane = c & 31, w = c >> 5;
    int run = 0;
    int t = 0;
    for (; t + 4 <= NB; t += 4) {
        int4 v = *(int4*)&g_bh[c][t];
        g_bh[c][t]     = run;          run += v.x;
        g_bh[c][t + 1] = run;          run += v.y;
        g_bh[c][t + 2] = run;          run += v.z;
        g_bh[c][t + 3] = run;          run += v.w;
    }
    for (; t < NB; t++) { int v = g_bh[c][t]; g_bh[c][t] = run; run += v; }

    int x = run;
#pragma unroll
    for (int off = 1; off < 32; off <<= 1) {
        int y = __shfl_up_sync(0xffffffffu, x, off);
        if (lane >= off) x += y;
    }
    __shared__ int wsum[4];
    if (lane == 31) wsum[w] = x;
    __syncthreads();
    int base = 0;
    for (int ww = 0; ww < w; ww++) base += wsum[ww];
    g_starts[c] = base + x - run;
}

// ---------------- K4: stable rank via match_any + per-warp prefix ---------------
__global__ void rank_order_kernel(const int* __restrict__ labels, int B) {
    __shared__ int warphist[16][C];
    const int tid = threadIdx.x;
    const int w = tid >> 5, lane = tid & 31;
    const int i = blockIdx.x * SORT_BLK + tid;

#pragma unroll
    for (int j = 0; j < (16 * C) / SORT_BLK; j++)
        ((int*)warphist)[tid + j * SORT_BLK] = 0;
    __syncthreads();

    int lab = -1, lane_rank = 0;
    if (i < B) {
        lab = labels[i];
        unsigned mask = __match_any_sync(__activemask(), lab);
        lane_rank = __popc(mask & ((1u << lane) - 1u));
        if ((__ffs(mask) - 1) == lane) warphist[w][lab] = __popc(mask);
    }
    __syncthreads();
    if (tid < C) {
        int run = 0;
#pragma unroll
        for (int ww = 0; ww < 16; ww++) {
            int v = warphist[ww][tid]; warphist[ww][tid] = run; run += v;
        }
    }
    __syncthreads();
    if (i < B) {
        const int rank = g_bh[lab][blockIdx.x] + warphist[w][lab] + lane_rank;
        g_rank[i] = rank;
        g_order[g_starts[lab] + rank] = i;
    }
}

// ---------------- K5: distances + hinge loss (sorted iteration for locality) ----
__global__ void dist_kernel(const float* __restrict__ emb,
                            const int*   __restrict__ labels,
                            const int*   __restrict__ r_pos,
                            const int*   __restrict__ r_neg,
                            int B) {
    __shared__ double s_loss;
    __shared__ int s_valid;
    if (threadIdx.x == 0) { s_loss = 0.0; s_valid = 0; }
    __syncthreads();

    const int lane = threadIdx.x & 31;
    const int j = (blockIdx.x * blockDim.x + threadIdx.x) >> 5;

    float loss = 0.0f;
    int valid = 0;

    if (j < B) {
        const int i = g_order[j];                // sorted order -> clustered gathers
        const int lab = labels[i];
        const int tn  = g_tneg[i];
        const int n_pos = g_counts[lab] - 1;
        const int n_neg = g_counts[tn];

        int pr = r_pos[i] % max(n_pos, 1);
        pr += (pr >= g_rank[i]) ? 1 : 0;
        const int pidx = g_order[min(g_starts[lab] + pr, B - 1)];
        const int nr = r_neg[i] % max(n_neg, 1);
        const int nidx = g_order[min(g_starts[tn] + nr, B - 1)];

        const float4* ei = (const float4*)(emb + (size_t)i    * D);
        const float4* ep = (const float4*)(emb + (size_t)pidx * D);
        const float4* en = (const float4*)(emb + (size_t)nidx * D);

        float dp = 0.0f, dn = 0.0f;
#pragma unroll
        for (int k = lane; k < D / 4; k += 32) {
            const float4 a = ei[k];
            const float4 p = ep[k];
            const float4 n4 = en[k];
            float dx;
            dx = a.x - p.x;  dp += dx * dx;
            dx = a.y - p.y;  dp += dx * dx;
            dx = a.z - p.z;  dp += dx * dx;
            dx = a.w - p.w;  dp += dx * dx;
            dx = a.x - n4.x; dn += dx * dx;
            dx = a.y - n4.y; dn += dx * dx;
            dx = a.z - n4.z; dn += dx * dx;
            dx = a.w - n4.w; dn += dx * dx;
        }
#pragma unroll
        for (int off = 16; off > 0; off >>= 1) {
            dp += __shfl_xor_sync(0xffffffffu, dp, off);
            dn += __shfl_xor_sync(0xffffffffu, dn, off);
        }
        if (lane == 0) {
            valid = (n_pos > 0 && n_neg > 0) ? 1 : 0;
            float l = sqrtf(dp) - sqrtf(dn) + 1.0f;   // MARGIN = 1.0
            loss = (l > 0.0f ? l : 0.0f) * (float)valid;
        }
    }
    if (lane == 0 && j < B) {
        atomicAdd(&s_loss, (double)loss);
        atomicAdd(&s_valid, valid);
    }
    __syncthreads();
    if (threadIdx.x == 0) {
        atomicAdd(&g_loss_sum, s_loss);
        atomicAdd(&g_valid_cnt, s_valid);
    }
}

// ---------------- K6: finalize scalar -------------------------------------------
__global__ void finalize_kernel(float* __restrict__ out) {
    out[0] = (float)(g_loss_sum / (double)max(g_valid_cnt, 1));
}

// ---------------- launch ---------------------------------------------------------
extern "C" void kernel_launch(void* const* d_in, const int* in_sizes, int n_in,
                              void* d_out, int out_size) {
    const float* emb    = (const float*)d_in[0];
    const int*   labels = (const int*)  d_in[1];
    const float* W      = (const float*)d_in[2];
    const float* b      = (const float*)d_in[3];
    const int*   r_pos  = (const int*)  d_in[4];
    const int*   r_neg  = (const int*)  d_in[5];
    float*       out    = (float*)d_out;

    const int B = in_sizes[1];

    cudaFuncSetAttribute(logits_top2_kernel,
                         cudaFuncAttributeMaxDynamicSharedMemorySize, GEMM_SMEM);

    init_kernel<<<1, 128>>>();
    prep_w_kernel<<<(C * D) / 256, 256>>>(W);

    logits_top2_kernel<<<(B + 127) / 128, 256, GEMM_SMEM>>>(emb, labels, b, B);

    const int NB = (B + SORT_BLK - 1) / SORT_BLK;
    hist_kernel<<<NB, SORT_BLK>>>(labels, B);
    scan_kernel<<<1, C>>>(NB);
    rank_order_kernel<<<NB, SORT_BLK>>>(labels, B);

    dist_kernel<<<(B + 7) / 8, 256>>>(emb, labels, r_pos, r_neg, B);
    finalize_kernel<<<1, 1>>>(out);
}

// round 4
// speedup vs baseline: 2.5456x; 1.0242x over previous
#include <cuda_runtime.h>
#include <cuda_bf16.h>
#include <math.h>
#include <float.h>
#include <stdint.h>

#define D 256
#define C 128
#define B_MAX 131072
#define SORT_BLK 512
#define NB_MAX (B_MAX / SORT_BLK)

// ---------------- scratch (static device globals; no allocation) ----------------
__device__ int    g_tneg[B_MAX];
__device__ int    g_rank[B_MAX];
__device__ int    g_order[B_MAX];
__device__ int    g_counts[C];
__device__ int    g_starts[C];
__device__ int    g_bh[C][NB_MAX];        // transposed block hist -> exclusive offsets
__device__ double g_loss_sum;
__device__ int    g_valid_cnt;
__device__ __align__(16) __nv_bfloat16 g_Whi[C * D];
__device__ __align__(16) __nv_bfloat16 g_Wlo[C * D];

// ---------------- prep: W split + zero accumulators (graph replays!) ------------
__global__ void prep_w_kernel(const float* __restrict__ W) {
    int i = blockIdx.x * 256 + threadIdx.x;   // grid covers C*D = 32768
    float f = W[i];
    __nv_bfloat16 h = __float2bfloat16(f);
    g_Whi[i] = h;
    g_Wlo[i] = __float2bfloat16(f - __bfloat162float(h));
    if (blockIdx.x == 0) {
        int t = threadIdx.x;
        if (t < C) g_counts[t] = 0;
        if (t == 0) { g_loss_sum = 0.0; g_valid_cnt = 0; }
    }
}

// ---------------- helpers ---------------------------------------------------------
__device__ __forceinline__ uint32_t smem_u32(const void* p) {
    uint32_t a;
    asm("{ .reg .u64 t; cvta.to.shared.u64 t, %1; cvt.u32.u64 %0, t; }" : "=r"(a) : "l"(p));
    return a;
}

__device__ __forceinline__ void top2_insert(float v, int idx,
                                            float& v1, int& i1, float& v2, int& i2) {
    if (v > v1 || (v == v1 && idx < i1)) {
        v2 = v1; i2 = i1; v1 = v; i1 = idx;
    } else if (v > v2 || (v == v2 && idx < i2)) {
        v2 = v; i2 = idx;
    }
}

__device__ __forceinline__ void mma16816(float* c, const uint32_t* a, const uint32_t* b) {
    asm volatile(
        "mma.sync.aligned.m16n8k16.row.col.f32.bf16.bf16.f32 "
        "{%0,%1,%2,%3}, {%4,%5,%6,%7}, {%8,%9}, {%0,%1,%2,%3};"
        : "+f"(c[0]), "+f"(c[1]), "+f"(c[2]), "+f"(c[3])
        : "r"(a[0]), "r"(a[1]), "r"(a[2]), "r"(a[3]), "r"(b[0]), "r"(b[1]));
}

__device__ __forceinline__ void ldsm_x4(uint32_t* r, uint32_t addr) {
    asm volatile("ldmatrix.sync.aligned.m8n8.x4.shared.b16 {%0,%1,%2,%3}, [%4];"
                 : "=r"(r[0]), "=r"(r[1]), "=r"(r[2]), "=r"(r[3]) : "r"(addr));
}

// x = lower-k element (low half), y = upper-k element (high half)
__device__ __forceinline__ void split2(float x, float y, uint32_t& h, uint32_t& l) {
    uint32_t hx;
    asm("cvt.rn.bf16x2.f32 %0, %1, %2;" : "=r"(hx) : "f"(y), "f"(x));
    float fx = __uint_as_float(hx << 16);
    float fy = __uint_as_float(hx & 0xFFFF0000u);
    float lx = x - fx, ly = y - fy;
    uint32_t lr;
    asm("cvt.rn.bf16x2.f32 %0, %1, %2;" : "=r"(lr) : "f"(ly), "f"(lx));
    h = hx; l = lr;
}

// =================== K1: HMMA bf16-split logits GEMM + top2 =====================
// CTA = 256 threads (8 warps), tile M=128 x N=128, K=256 (4 chunks of 64).
// smem: bias 512 | red 4096 | Whi/Wlo resident (stride 528) | A fp32 dbl-buf (stride 288)
#define W_STRIDE 528
#define A_STRIDE 288
#define OFF_RED  512
#define OFF_WHI  4608
#define OFF_WLO  (OFF_WHI + 128 * W_STRIDE)      // 72192
#define OFF_A0   (OFF_WLO + 128 * W_STRIDE)      // 139776
#define OFF_A1   (OFF_A0 + 128 * A_STRIDE)       // 176640
#define GEMM_SMEM (OFF_A1 + 128 * A_STRIDE)      // 213504 B

__device__ __forceinline__ void cp_chunk(uint32_t dst_base, const float* __restrict__ emb,
                                         int mBase, int c, int B, int tid) {
#pragma unroll
    for (int it = 0; it < 8; it++) {
        int gi = it * 256 + tid;       // 2048 groups of 4 floats (16B)
        int row = gi >> 4;
        int k4 = (gi & 15) * 4;
        int gr = mBase + row; if (gr >= B) gr = B - 1;
        const float* src = emb + (size_t)gr * D + c * 64 + k4;
        uint32_t dst = dst_base + row * A_STRIDE + k4 * 4;
        asm volatile("cp.async.cg.shared.global [%0], [%1], 16;" :: "r"(dst), "l"(src));
    }
}

__global__ void __launch_bounds__(256, 1)
logits_top2_kernel(const float* __restrict__ emb,
                   const int*   __restrict__ labels,
                   const float* __restrict__ b,
                   int B) {
    extern __shared__ char smem[];
    const uint32_t sb = smem_u32(smem);
    float* sm_bias = (float*)smem;                       // 128 floats
    float* red_v1  = (float*)(smem + OFF_RED);           // [2][128]
    int*   red_i1  = (int*)  (smem + OFF_RED + 1024);
    float* red_v2  = (float*)(smem + OFF_RED + 2048);
    int*   red_i2  = (int*)  (smem + OFF_RED + 3072);

    const int tid = threadIdx.x;
    const int wid = tid >> 5, lane = tid & 31;
    const int warp_m = wid & 3, warp_n = wid >> 2;
    const int g = lane >> 2, t = lane & 3;
    const int m0 = warp_m * 32, n0 = warp_n * 64;
    const int mBase = blockIdx.x * 128;

    if (tid < C) sm_bias[tid] = b[tid];

    // W hi/lo -> smem once (bf16, padded stride)
#pragma unroll
    for (int it = 0; it < 16; it++) {
        int gi = it * 256 + tid;       // 4096 groups of 8 bf16 (16B)
        int row = gi >> 5;
        int k8 = (gi & 31) * 8;
        *(uint4*)(smem + OFF_WHI + row * W_STRIDE + k8 * 2) =
            *(const uint4*)(g_Whi + row * D + k8);
        *(uint4*)(smem + OFF_WLO + row * W_STRIDE + k8 * 2) =
            *(const uint4*)(g_Wlo + row * D + k8);
    }

    // A chunk 0 prefetch
    cp_chunk(sb + OFF_A0, emb, mBase, 0, B, tid);
    asm volatile("cp.async.commit_group;");

    float acc[2][8][4];
#pragma unroll
    for (int mi = 0; mi < 2; mi++)
#pragma unroll
        for (int ni = 0; ni < 8; ni++)
#pragma unroll
            for (int cc = 0; cc < 4; cc++) acc[mi][ni][cc] = 0.0f;

    const int wr = (lane & 7) + ((lane >> 3) & 1) * 8;       // ldmatrix row-in-16
    const int kbh = ((lane >> 4) & 1) * 16;                  // ldmatrix k-half byte

#pragma unroll 1
    for (int c = 0; c < 4; c++) {
        const uint32_t curOff = (c & 1) ? OFF_A1 : OFF_A0;
        const uint32_t nxtOff = (c & 1) ? OFF_A0 : OFF_A1;
        if (c < 3) cp_chunk(sb + nxtOff, emb, mBase, c + 1, B, tid);
        asm volatile("cp.async.commit_group;");              // empty group OK at c==3
        asm volatile("cp.async.wait_group 1;");
        __syncthreads();

#pragma unroll
        for (int ks = 0; ks < 4; ks++) {
            // A fragments: fp32 LDS.64 + on-the-fly hi/lo split
            uint32_t ahi[2][4], alo[2][4];
#pragma unroll
            for (int mi = 0; mi < 2; mi++) {
#pragma unroll
                for (int r = 0; r < 4; r++) {
                    int row = m0 + mi * 16 + g + (r & 1) * 8;
                    int ke  = ks * 16 + (r >> 1) * 8 + 2 * t;
                    const float2 v = *(const float2*)(smem + curOff + row * A_STRIDE + ke * 4);
                    split2(v.x, v.y, ahi[mi][r], alo[mi][r]);
                }
            }
            // W fragments via ldmatrix.x4 (n16 x k16 each)
            uint32_t bhi[4][4], blo[4][4];
            const int kb = c * 128 + ks * 32 + kbh;
#pragma unroll
            for (int p = 0; p < 4; p++) {
                int nrow = n0 + p * 16 + wr;
                ldsm_x4(bhi[p], sb + OFF_WHI + nrow * W_STRIDE + kb);
                ldsm_x4(blo[p], sb + OFF_WLO + nrow * W_STRIDE + kb);
            }
            // 3 numeric passes fused: hi*hi + lo*hi + hi*lo
#pragma unroll
            for (int mi = 0; mi < 2; mi++)
#pragma unroll
                for (int ni = 0; ni < 8; ni++) {
                    const int p = ni >> 1, hh = ni & 1;
                    uint32_t bh[2] = { bhi[p][hh], bhi[p][hh + 2] };
                    uint32_t bl[2] = { blo[p][hh], blo[p][hh + 2] };
                    mma16816(acc[mi][ni], ahi[mi], bh);
                    mma16816(acc[mi][ni], alo[mi], bh);
                    mma16816(acc[mi][ni], ahi[mi], bl);
                }
        }
        __syncthreads();
    }

    // Epilogue: per-thread top2, quad-reduce, cross-warp_n merge.
#pragma unroll
    for (int mi = 0; mi < 2; mi++) {
#pragma unroll
        for (int rh = 0; rh < 2; rh++) {
            float v1 = -FLT_MAX, v2 = -FLT_MAX;
            int i1 = 0x7fffffff, i2 = 0x7fffffff;
#pragma unroll
            for (int ni = 0; ni < 8; ni++) {
#pragma unroll
                for (int cc = 0; cc < 2; cc++) {
                    int col = n0 + ni * 8 + 2 * t + cc;
                    float v = acc[mi][ni][rh * 2 + cc] + sm_bias[col];
                    top2_insert(v, col, v1, i1, v2, i2);
                }
            }
#pragma unroll
            for (int off = 1; off < 4; off <<= 1) {
                float ov1 = __shfl_xor_sync(0xffffffffu, v1, off);
                int   oi1 = __shfl_xor_sync(0xffffffffu, i1, off);
                float ov2 = __shfl_xor_sync(0xffffffffu, v2, off);
                int   oi2 = __shfl_xor_sync(0xffffffffu, i2, off);
                top2_insert(ov1, oi1, v1, i1, v2, i2);
                top2_insert(ov2, oi2, v1, i1, v2, i2);
            }
            if (t == 0) {
                int row = m0 + mi * 16 + rh * 8 + g;
                red_v1[warp_n * 128 + row] = v1;
                red_i1[warp_n * 128 + row] = i1;
                red_v2[warp_n * 128 + row] = v2;
                red_i2[warp_n * 128 + row] = i2;
            }
        }
    }
    __syncthreads();

    if (tid < 128) {
        const int row = tid;
        float v1 = red_v1[row];
        int   i1 = red_i1[row];
        float v2 = red_v2[row];
        int   i2 = red_i2[row];
        top2_insert(red_v1[128 + row], red_i1[128 + row], v1, i1, v2, i2);
        top2_insert(red_v2[128 + row], red_i2[128 + row], v1, i1, v2, i2);
        const int gr = mBase + row;
        if (gr < B) {
            int lab = labels[gr];
            g_tneg[gr] = (i1 == lab) ? i2 : i1;
        }
    }
}

// ---------------- K2: per-block label histogram (transposed) --------------------
__global__ void hist_kernel(const int* __restrict__ labels, int B) {
    __shared__ int h[C];
    const int tid = threadIdx.x;
    if (tid < C) h[tid] = 0;
    __syncthreads();
    const int i = blockIdx.x * SORT_BLK + tid;
    if (i < B) atomicAdd(&h[labels[i]], 1);
    __syncthreads();
    if (tid < C) {
        g_bh[tid][blockIdx.x] = h[tid];
        atomicAdd(&g_counts[tid], h[tid]);
    }
}

// ---------------- K3: per-class exclusive scan over blocks + starts -------------
__global__ void scan_kernel(int NB) {
    const int c = threadIdx.x;          // 128 threads
    const int lane = c & 31, w = c >> 5;
    int run = 0;
    int t = 0;
    for (; t + 4 <= NB; t += 4) {
        int4 v = *(int4*)&g_bh[c][t];
        g_bh[c][t]     = run;          run += v.x;
        g_bh[c][t + 1] = run;          run += v.y;
        g_bh[c][t + 2] = run;          run += v.z;
        g_bh[c][t + 3] = run;          run += v.w;
    }
    for (; t < NB; t++) { int v = g_bh[c][t]; g_bh[c][t] = run; run += v; }

    int x = run;
#pragma unroll
    for (int off = 1; off < 32; off <<= 1) {
        int y = __shfl_up_sync(0xffffffffu, x, off);
        if (lane >= off) x += y;
    }
    __shared__ int wsum[4];
    if (lane == 31) wsum[w] = x;
    __syncthreads();
    int base = 0;
    for (int ww = 0; ww < w; ww++) base += wsum[ww];
    g_starts[c] = base + x - run;
}

// ---------------- K4: stable rank via match_any + per-warp prefix ---------------
__global__ void rank_order_kernel(const int* __restrict__ labels, int B) {
    __shared__ int warphist[16][C];
    const int tid = threadIdx.x;
    const int w = tid >> 5, lane = tid & 31;
    const int i = blockIdx.x * SORT_BLK + tid;

#pragma unroll
    for (int j = 0; j < (16 * C) / SORT_BLK; j++)
        ((int*)warphist)[tid + j * SORT_BLK] = 0;
    __syncthreads();

    int lab = -1, lane_rank = 0;
    if (i < B) {
        lab = labels[i];
        unsigned mask = __match_any_sync(__activemask(), lab);
        lane_rank = __popc(mask & ((1u << lane) - 1u));
        if ((__ffs(mask) - 1) == lane) warphist[w][lab] = __popc(mask);
    }
    __syncthreads();
    if (tid < C) {
        int run = 0;
#pragma unroll
        for (int ww = 0; ww < 16; ww++) {
            int v = warphist[ww][tid]; warphist[ww][tid] = run; run += v;
        }
    }
    __syncthreads();
    if (i < B) {
        const int rank = g_bh[lab][blockIdx.x] + warphist[w][lab] + lane_rank;
        g_rank[i] = rank;
        g_order[g_starts[lab] + rank] = i;
    }
}

// ---------------- K5: distances + hinge loss (sorted iteration for locality) ----
__global__ void dist_kernel(const float* __restrict__ emb,
                            const int*   __restrict__ labels,
                            const int*   __restrict__ r_pos,
                            const int*   __restrict__ r_neg,
                            int B) {
    __shared__ double s_loss;
    __shared__ int s_valid;
    if (threadIdx.x == 0) { s_loss = 0.0; s_valid = 0; }
    __syncthreads();

    const int lane = threadIdx.x & 31;
    const int j = (blockIdx.x * blockDim.x + threadIdx.x) >> 5;

    float loss = 0.0f;
    int valid = 0;

    if (j < B) {
        const int i = g_order[j];                // sorted order -> clustered gathers
        const int lab = labels[i];
        const int tn  = g_tneg[i];
        const int n_pos = g_counts[lab] - 1;
        const int n_neg = g_counts[tn];

        int pr = r_pos[i] % max(n_pos, 1);
        pr += (pr >= g_rank[i]) ? 1 : 0;
        const int pidx = g_order[min(g_starts[lab] + pr, B - 1)];
        const int nr = r_neg[i] % max(n_neg, 1);
        const int nidx = g_order[min(g_starts[tn] + nr, B - 1)];

        const float4* ei = (const float4*)(emb + (size_t)i    * D);
        const float4* ep = (const float4*)(emb + (size_t)pidx * D);
        const float4* en = (const float4*)(emb + (size_t)nidx * D);

        float dp = 0.0f, dn = 0.0f;
#pragma unroll
        for (int k = lane; k < D / 4; k += 32) {
            const float4 a = ei[k];
            const float4 p = ep[k];
            const float4 n4 = en[k];
            float dx;
            dx = a.x - p.x;  dp += dx * dx;
            dx = a.y - p.y;  dp += dx * dx;
            dx = a.z - p.z;  dp += dx * dx;
            dx = a.w - p.w;  dp += dx * dx;
            dx = a.x - n4.x; dn += dx * dx;
            dx = a.y - n4.y; dn += dx * dx;
            dx = a.z - n4.z; dn += dx * dx;
            dx = a.w - n4.w; dn += dx * dx;
        }
#pragma unroll
        for (int off = 16; off > 0; off >>= 1) {
            dp += __shfl_xor_sync(0xffffffffu, dp, off);
            dn += __shfl_xor_sync(0xffffffffu, dn, off);
        }
        if (lane == 0) {
            valid = (n_pos > 0 && n_neg > 0) ? 1 : 0;
            float l = sqrtf(dp) - sqrtf(dn) + 1.0f;   // MARGIN = 1.0
            loss = (l > 0.0f ? l : 0.0f) * (float)valid;
        }
    }
    if (lane == 0 && j < B) {
        atomicAdd(&s_loss, (double)loss);
        atomicAdd(&s_valid, valid);
    }
    __syncthreads();
    if (threadIdx.x == 0) {
        atomicAdd(&g_loss_sum, s_loss);
        atomicAdd(&g_valid_cnt, s_valid);
    }
}

// ---------------- K6: finalize scalar -------------------------------------------
__global__ void finalize_kernel(float* __restrict__ out) {
    out[0] = (float)(g_loss_sum / (double)max(g_valid_cnt, 1));
}

// ---------------- launch ---------------------------------------------------------
extern "C" void kernel_launch(void* const* d_in, const int* in_sizes, int n_in,
                              void* d_out, int out_size) {
    const float* emb    = (const float*)d_in[0];
    const int*   labels = (const int*)  d_in[1];
    const float* W      = (const float*)d_in[2];
    const float* b      = (const float*)d_in[3];
    const int*   r_pos  = (const int*)  d_in[4];
    const int*   r_neg  = (const int*)  d_in[5];
    float*       out    = (float*)d_out;

    const int B = in_sizes[1];

    cudaFuncSetAttribute(logits_top2_kernel,
                         cudaFuncAttributeMaxDynamicSharedMemorySize, GEMM_SMEM);

    prep_w_kernel<<<(C * D) / 256, 256>>>(W);

    logits_top2_kernel<<<(B + 127) / 128, 256, GEMM_SMEM>>>(emb, labels, b, B);

    const int NB = (B + SORT_BLK - 1) / SORT_BLK;
    hist_kernel<<<NB, SORT_BLK>>>(labels, B);
    scan_kernel<<<1, C>>>(NB);
    rank_order_kernel<<<NB, SORT_BLK>>>(labels, B);

    dist_kernel<<<(B + 7) / 8, 256>>>(emb, labels, r_pos, r_neg, B);
    finalize_kernel<<<1, 1>>>(out);
}